// round 1
// baseline (speedup 1.0000x reference)
#include <cuda_runtime.h>
#include <math.h>

#define B_  2
#define S_  2048
#define D_  1024
#define H_  16
#define HD  64
#define M_  (B_ * S_)   /* 4096 rows */

// ---------------- scratch (allocation-free rule: __device__ globals) ----------------
__device__ float g_xpe[M_ * D_];   // x + mixed positional encoding
__device__ float g_q[M_ * D_];     // [B,H,S,hd]
__device__ float g_k[M_ * D_];     // [B,H,S,hd]
__device__ float g_v[M_ * D_];     // [B,H,S,hd]
__device__ float g_att[M_ * D_];   // attention output, [B,S,D]

// ==================================================================================
// Kernel 1: x + alpha*sinusoid_pe + (1-alpha)*rel_emb[2952+s]
// grid: (4096), block: 256; each thread one float4 of a (b,s) row.
// ==================================================================================
__global__ void add_pe_kernel(const float* __restrict__ x,
                              const float* __restrict__ rel,
                              const float* __restrict__ alpha_p)
{
    int bs  = blockIdx.x;           // 0..4095
    int s   = bs & (S_ - 1);
    int col = threadIdx.x << 2;     // 0,4,...,1020
    float a  = *alpha_p;
    float na = 1.0f - a;

    // div = exp(arange(0,D,2) * (-ln(10000)/D)); pe[2i]=sin(pos*div[i]), pe[2i+1]=cos
    const float C = -0.0089944731f; // -ln(10000)/1024 in fp32
    float d0 = expf((float)col * C);         // exponent arg 2*i0 = col
    float d1 = expf((float)(col + 2) * C);   // 2*i1 = col+2
    float fs = (float)s;
    float ang0 = fs * d0;
    float ang1 = fs * d1;

    const float4 xin = *(const float4*)(x + (size_t)bs * D_ + col);
    const float4 rin = *(const float4*)(rel + (size_t)(2952 + s) * D_ + col);

    float4 o;
    o.x = xin.x + a * sinf(ang0) + na * rin.x;
    o.y = xin.y + a * cosf(ang0) + na * rin.y;
    o.z = xin.z + a * sinf(ang1) + na * rin.z;
    o.w = xin.w + a * cosf(ang1) + na * rin.w;
    *(float4*)(g_xpe + (size_t)bs * D_ + col) = o;
}

// ==================================================================================
// Kernel 2: C = X @ W^T + bias.  X:[4096,1024] row-major, W:[1024,1024] row-major.
// mode==1: X=g_xpe, z-indexed (Wq/Wk/Wv), epilogue scatters into [B,H,S,hd].
// mode==0: X=g_att, single W (Wo), plain row-major store to outp.
// 128x128x32 tiles, 256 threads, 8x8 microtile.
// ==================================================================================
__global__ void __launch_bounds__(256, 2) gemm_kernel(
    int mode,
    const float* __restrict__ Wa, const float* __restrict__ Wb, const float* __restrict__ Wc,
    const float* __restrict__ Ba, const float* __restrict__ Bb, const float* __restrict__ Bc,
    float* __restrict__ outp)
{
    __shared__ float As[32][132];   // [k][m], stride 132: aligned float4 rows, cf loads
    __shared__ float Bs[32][132];   // [k][n]

    const float* X    = mode ? g_xpe : g_att;
    int z             = blockIdx.z;
    const float* W    = (z == 0) ? Wa : ((z == 1) ? Wb : Wc);
    const float* bias = (z == 0) ? Ba : ((z == 1) ? Bb : Bc);
    float* outs       = mode ? ((z == 0) ? g_q : ((z == 1) ? g_k : g_v)) : outp;

    int m0 = blockIdx.y * 128;
    int n0 = blockIdx.x * 128;
    int t  = threadIdx.x;
    int lr = t >> 3;     // 0..31 (row within 32-row chunk)
    int lc = t & 7;      // 0..7  (k float4 group)
    int tx = t & 15;     // n-dir thread coord
    int ty = t >> 4;     // m-dir thread coord

    float acc[8][8];
#pragma unroll
    for (int i = 0; i < 8; i++)
#pragma unroll
        for (int j = 0; j < 8; j++) acc[i][j] = 0.0f;

    for (int k0 = 0; k0 < 1024; k0 += 32) {
#pragma unroll
        for (int p = 0; p < 4; p++) {
            int row  = m0 + lr + p * 32;
            float4 va = *(const float4*)(X + (size_t)row * 1024 + k0 + lc * 4);
            As[lc * 4 + 0][lr + p * 32] = va.x;
            As[lc * 4 + 1][lr + p * 32] = va.y;
            As[lc * 4 + 2][lr + p * 32] = va.z;
            As[lc * 4 + 3][lr + p * 32] = va.w;
            int wrow = n0 + lr + p * 32;
            float4 vb = *(const float4*)(W + (size_t)wrow * 1024 + k0 + lc * 4);
            Bs[lc * 4 + 0][lr + p * 32] = vb.x;
            Bs[lc * 4 + 1][lr + p * 32] = vb.y;
            Bs[lc * 4 + 2][lr + p * 32] = vb.z;
            Bs[lc * 4 + 3][lr + p * 32] = vb.w;
        }
        __syncthreads();
#pragma unroll
        for (int kk = 0; kk < 32; kk++) {
            float4 a0 = *(const float4*)&As[kk][ty * 8];
            float4 a1 = *(const float4*)&As[kk][ty * 8 + 4];
            float4 b0 = *(const float4*)&Bs[kk][tx * 8];
            float4 b1 = *(const float4*)&Bs[kk][tx * 8 + 4];
            float av[8] = {a0.x, a0.y, a0.z, a0.w, a1.x, a1.y, a1.z, a1.w};
            float bw[8] = {b0.x, b0.y, b0.z, b0.w, b1.x, b1.y, b1.z, b1.w};
#pragma unroll
            for (int i = 0; i < 8; i++)
#pragma unroll
                for (int j = 0; j < 8; j++)
                    acc[i][j] += av[i] * bw[j];
        }
        __syncthreads();
    }

    float bb[8];
#pragma unroll
    for (int j = 0; j < 8; j++) bb[j] = bias[n0 + tx * 8 + j];

#pragma unroll
    for (int i = 0; i < 8; i++) {
        int m = m0 + ty * 8 + i;
        float4 v0 = make_float4(acc[i][0] + bb[0], acc[i][1] + bb[1],
                                acc[i][2] + bb[2], acc[i][3] + bb[3]);
        float4 v1 = make_float4(acc[i][4] + bb[4], acc[i][5] + bb[5],
                                acc[i][6] + bb[6], acc[i][7] + bb[7]);
        float* op;
        if (mode) {
            int b_   = m >> 11;
            int srow = m & 2047;
            int nb   = n0 + tx * 8;       // 8-aligned -> no 64-boundary crossing
            int h    = nb >> 6;
            int d    = nb & 63;
            op = outs + (((size_t)(b_ * H_ + h) * S_ + srow) * HD + d);
        } else {
            op = outs + (size_t)m * 1024 + n0 + tx * 8;
        }
        *(float4*)op       = v0;
        *(float4*)(op + 4) = v1;
    }
}

// ==================================================================================
// Kernel 3: flash attention, fp32. One block = (bh, 64-query tile). 256 threads.
// Thread (r=t/4, c=t&3): owns query row r; k-slice c*16..c*16+15 for scores,
// d-slice c*16..c*16+15 for output. P reuses K smem buffer.
// ==================================================================================
__global__ void attn_kernel()
{
    __shared__ float Ks[64 * 68];   // stride 68: float4-aligned rows; reused for P
    __shared__ float Vs[64 * 64];

    int bh = blockIdx.y;            // 0..31 = b*16 + h
    int q0 = blockIdx.x * 64;
    const float* qp = g_q + (size_t)bh * (S_ * HD);
    const float* kp = g_k + (size_t)bh * (S_ * HD);
    const float* vp = g_v + (size_t)bh * (S_ * HD);

    int t = threadIdx.x;
    int r = t >> 2;                 // 0..63 query row
    int c = t & 3;                  // k/d quarter

    float Qreg[16];
    {
        const float4* q4 = (const float4*)(qp + (size_t)(q0 + r) * HD + c * 16);
#pragma unroll
        for (int u = 0; u < 4; u++) {
            float4 tmp = q4[u];
            Qreg[u * 4 + 0] = tmp.x; Qreg[u * 4 + 1] = tmp.y;
            Qreg[u * 4 + 2] = tmp.z; Qreg[u * 4 + 3] = tmp.w;
        }
    }

    const float SCALE = 0.03125f;   // 1/sqrt(1024)
    float m = -INFINITY, l = 0.0f;
    float O[16];
#pragma unroll
    for (int u = 0; u < 16; u++) O[u] = 0.0f;

    for (int tile = 0; tile < 32; ++tile) {
        int k0 = tile * 64;
        // ---- load K,V tiles (64x64 each) ----
#pragma unroll
        for (int p = 0; p < 4; p++) {
            int idx = t + p * 256;          // 0..1023 float4s
            int row = idx >> 4;
            int cg  = idx & 15;
            float4 kv = *(const float4*)(kp + (size_t)(k0 + row) * HD + cg * 4);
            Ks[row * 68 + cg * 4 + 0] = kv.x;
            Ks[row * 68 + cg * 4 + 1] = kv.y;
            Ks[row * 68 + cg * 4 + 2] = kv.z;
            Ks[row * 68 + cg * 4 + 3] = kv.w;
            float4 vv = *(const float4*)(vp + (size_t)(k0 + row) * HD + cg * 4);
            *(float4*)&Vs[row * 64 + cg * 4] = vv;
        }
        __syncthreads();

        // ---- S = Q K^T * scale (4-lane partial dots + shfl reduce) ----
        float sj[16];
        float tmax = -INFINITY;
#pragma unroll
        for (int jj = 0; jj < 16; jj++) {
#pragma unroll
            for (int cc = 0; cc < 4; cc++) {
                int j = jj * 4 + cc;
                const float* kr = &Ks[j * 68 + c * 16];
                float part = 0.0f;
#pragma unroll
                for (int dd = 0; dd < 16; dd += 4) {
                    float4 k4 = *(const float4*)(kr + dd);
                    part += Qreg[dd]     * k4.x;
                    part += Qreg[dd + 1] * k4.y;
                    part += Qreg[dd + 2] * k4.z;
                    part += Qreg[dd + 3] * k4.w;
                }
                part += __shfl_xor_sync(0xffffffffu, part, 1);
                part += __shfl_xor_sync(0xffffffffu, part, 2);
                float sv = part * SCALE;
                if (cc == c) sj[jj] = sv;
                tmax = fmaxf(tmax, sv);     // identical across the 4 lanes
            }
        }

        // ---- online softmax update ----
        float mnew = fmaxf(m, tmax);
        float corr = __expf(m - mnew);      // exp(-inf)=0 on first tile
        float tsum = 0.0f;
#pragma unroll
        for (int jj = 0; jj < 16; jj++) {
            float pv = __expf(sj[jj] - mnew);
            sj[jj] = pv;
            tsum  += pv;
        }
        tsum += __shfl_xor_sync(0xffffffffu, tsum, 1);
        tsum += __shfl_xor_sync(0xffffffffu, tsum, 2);
        l = l * corr + tsum;
        m = mnew;
#pragma unroll
        for (int u = 0; u < 16; u++) O[u] *= corr;

        __syncthreads();                    // everyone done reading Ks
        // ---- write P into Ks buffer ----
#pragma unroll
        for (int jj = 0; jj < 16; jj++)
            Ks[r * 68 + jj * 4 + c] = sj[jj];
        __syncthreads();

        // ---- O += P @ V ----
        for (int j = 0; j < 64; j++) {
            float pj = Ks[r * 68 + j];
            const float4* vrow = (const float4*)&Vs[j * 64 + c * 16];
#pragma unroll
            for (int d4 = 0; d4 < 4; d4++) {
                float4 vv = vrow[d4];
                O[d4 * 4 + 0] += pj * vv.x;
                O[d4 * 4 + 1] += pj * vv.y;
                O[d4 * 4 + 2] += pj * vv.z;
                O[d4 * 4 + 3] += pj * vv.w;
            }
        }
        __syncthreads();                    // before next tile overwrites Ks/Vs
    }

    // ---- epilogue: write [B,S,D] layout for the O-projection GEMM ----
    float inv = 1.0f / l;
    int b_ = bh >> 4;
    int h  = bh & 15;
    float* op = g_att + (size_t)(b_ * S_ + q0 + r) * D_ + h * HD + c * 16;
#pragma unroll
    for (int d4 = 0; d4 < 4; d4++) {
        float4 vv = make_float4(O[d4 * 4 + 0] * inv, O[d4 * 4 + 1] * inv,
                                O[d4 * 4 + 2] * inv, O[d4 * 4 + 3] * inv);
        ((float4*)op)[d4] = vv;
    }
}

// ==================================================================================
extern "C" void kernel_launch(void* const* d_in, const int* in_sizes, int n_in,
                              void* d_out, int out_size)
{
    const float* x     = (const float*)d_in[0];
    const float* rel   = (const float*)d_in[1];
    const float* alpha = (const float*)d_in[2];
    const float* Wq    = (const float*)d_in[3];
    const float* bq    = (const float*)d_in[4];
    const float* Wk    = (const float*)d_in[5];
    const float* bk    = (const float*)d_in[6];
    const float* Wv    = (const float*)d_in[7];
    const float* bv    = (const float*)d_in[8];
    const float* Wo    = (const float*)d_in[9];
    const float* bo    = (const float*)d_in[10];
    float* out = (float*)d_out;

    add_pe_kernel<<<M_, 256>>>(x, rel, alpha);
    gemm_kernel<<<dim3(8, 32, 3), 256>>>(1, Wq, Wk, Wv, bq, bk, bv, nullptr);
    attn_kernel<<<dim3(32, 32), 256>>>();
    gemm_kernel<<<dim3(8, 32, 1), 256>>>(0, Wo, Wo, Wo, bo, bo, bo, out);
}

// round 4
// speedup vs baseline: 2.6353x; 2.6353x over previous
#include <cuda_runtime.h>
#include <math.h>

#define B_  2
#define S_  2048
#define D_  1024
#define H_  16
#define HD  64
#define M_  (B_ * S_)   /* 4096 rows */

// ---------------- scratch (allocation-free rule: __device__ globals) ----------------
__device__ float g_xpe[M_ * D_];   // x + mixed positional encoding
__device__ float g_q[M_ * D_];     // [B,H,HD,S]  (TRANSPOSED: d-major)
__device__ float g_k[M_ * D_];     // [B,H,HD,S]  (TRANSPOSED: d-major)
__device__ float g_v[M_ * D_];     // [B,H,S,HD]  (natural)
__device__ float g_att[M_ * D_];   // attention output, [B,S,D]

// ==================================================================================
// Kernel 1: x + alpha*sinusoid_pe + (1-alpha)*rel_emb[2952+s]
// ==================================================================================
__global__ void add_pe_kernel(const float* __restrict__ x,
                              const float* __restrict__ rel,
                              const float* __restrict__ alpha_p)
{
    int bs  = blockIdx.x;           // 0..4095
    int s   = bs & (S_ - 1);
    int col = threadIdx.x << 2;     // 0,4,...,1020
    float a  = *alpha_p;
    float na = 1.0f - a;

    const float C = -0.0089944731f; // -ln(10000)/1024
    float d0 = expf((float)col * C);
    float d1 = expf((float)(col + 2) * C);
    float fs = (float)s;
    float ang0 = fs * d0;
    float ang1 = fs * d1;

    const float4 xin = *(const float4*)(x + (size_t)bs * D_ + col);
    const float4 rin = *(const float4*)(rel + (size_t)(2952 + s) * D_ + col);

    float4 o;
    o.x = xin.x + a * sinf(ang0) + na * rin.x;
    o.y = xin.y + a * cosf(ang0) + na * rin.y;
    o.z = xin.z + a * sinf(ang1) + na * rin.z;
    o.w = xin.w + a * cosf(ang1) + na * rin.w;
    *(float4*)(g_xpe + (size_t)bs * D_ + col) = o;
}

// ==================================================================================
// Kernel 2: C = X @ W^T + bias.
// mode==1: X=g_xpe; z = 0/1/2 -> Q/K/V. Q,K stored TRANSPOSED [b,h,d,s];
//          V stored natural [b,h,s,d].
// mode==0: X=g_att, W=Wo, plain row-major store to outp.
// ==================================================================================
__global__ void __launch_bounds__(256, 2) gemm_kernel(
    int mode,
    const float* __restrict__ Wa, const float* __restrict__ Wb, const float* __restrict__ Wc,
    const float* __restrict__ Ba, const float* __restrict__ Bb, const float* __restrict__ Bc,
    float* __restrict__ outp)
{
    __shared__ float As[32][132];
    __shared__ float Bs[32][132];

    const float* X    = mode ? g_xpe : g_att;
    int z             = blockIdx.z;
    const float* W    = (z == 0) ? Wa : ((z == 1) ? Wb : Wc);
    const float* bias = (z == 0) ? Ba : ((z == 1) ? Bb : Bc);
    float* outs       = mode ? ((z == 0) ? g_q : ((z == 1) ? g_k : g_v)) : outp;

    int m0 = blockIdx.y * 128;
    int n0 = blockIdx.x * 128;
    int t  = threadIdx.x;
    int lr = t >> 3;
    int lc = t & 7;
    int tx = t & 15;
    int ty = t >> 4;

    float acc[8][8];
#pragma unroll
    for (int i = 0; i < 8; i++)
#pragma unroll
        for (int j = 0; j < 8; j++) acc[i][j] = 0.0f;

    for (int k0 = 0; k0 < 1024; k0 += 32) {
#pragma unroll
        for (int p = 0; p < 4; p++) {
            int row  = m0 + lr + p * 32;
            float4 va = *(const float4*)(X + (size_t)row * 1024 + k0 + lc * 4);
            As[lc * 4 + 0][lr + p * 32] = va.x;
            As[lc * 4 + 1][lr + p * 32] = va.y;
            As[lc * 4 + 2][lr + p * 32] = va.z;
            As[lc * 4 + 3][lr + p * 32] = va.w;
            int wrow = n0 + lr + p * 32;
            float4 vb = *(const float4*)(W + (size_t)wrow * 1024 + k0 + lc * 4);
            Bs[lc * 4 + 0][lr + p * 32] = vb.x;
            Bs[lc * 4 + 1][lr + p * 32] = vb.y;
            Bs[lc * 4 + 2][lr + p * 32] = vb.z;
            Bs[lc * 4 + 3][lr + p * 32] = vb.w;
        }
        __syncthreads();
#pragma unroll
        for (int kk = 0; kk < 32; kk++) {
            float4 a0 = *(const float4*)&As[kk][ty * 8];
            float4 a1 = *(const float4*)&As[kk][ty * 8 + 4];
            float4 b0 = *(const float4*)&Bs[kk][tx * 8];
            float4 b1 = *(const float4*)&Bs[kk][tx * 8 + 4];
            float av[8] = {a0.x, a0.y, a0.z, a0.w, a1.x, a1.y, a1.z, a1.w};
            float bw[8] = {b0.x, b0.y, b0.z, b0.w, b1.x, b1.y, b1.z, b1.w};
#pragma unroll
            for (int i = 0; i < 8; i++)
#pragma unroll
                for (int j = 0; j < 8; j++)
                    acc[i][j] += av[i] * bw[j];
        }
        __syncthreads();
    }

    float bb[8];
#pragma unroll
    for (int j = 0; j < 8; j++) bb[j] = bias[n0 + tx * 8 + j];

    if (mode && z < 2) {
        // ---- transposed store: out[b][h][d][s], s contiguous ----
        int b_ = m0 >> 11;
        int s0 = (m0 & 2047) + ty * 8;       // 8-aligned
#pragma unroll
        for (int j = 0; j < 8; j++) {
            int nb = n0 + tx * 8 + j;
            int h  = nb >> 6;
            int d  = nb & 63;
            float4 w0 = make_float4(acc[0][j] + bb[j], acc[1][j] + bb[j],
                                    acc[2][j] + bb[j], acc[3][j] + bb[j]);
            float4 w1 = make_float4(acc[4][j] + bb[j], acc[5][j] + bb[j],
                                    acc[6][j] + bb[j], acc[7][j] + bb[j]);
            float* op = outs + ((size_t)((b_ * H_ + h) * HD + d)) * S_ + s0;
            *(float4*)op       = w0;
            *(float4*)(op + 4) = w1;
        }
    } else {
#pragma unroll
        for (int i = 0; i < 8; i++) {
            int m = m0 + ty * 8 + i;
            float4 v0 = make_float4(acc[i][0] + bb[0], acc[i][1] + bb[1],
                                    acc[i][2] + bb[2], acc[i][3] + bb[3]);
            float4 v1 = make_float4(acc[i][4] + bb[4], acc[i][5] + bb[5],
                                    acc[i][6] + bb[6], acc[i][7] + bb[7]);
            float* op;
            if (mode) {
                int b_   = m >> 11;
                int srow = m & 2047;
                int nb   = n0 + tx * 8;
                int h    = nb >> 6;
                int d    = nb & 63;
                op = outs + (((size_t)(b_ * H_ + h) * S_ + srow) * HD + d);
            } else {
                op = outs + (size_t)m * 1024 + n0 + tx * 8;
            }
            *(float4*)op       = v0;
            *(float4*)(op + 4) = v1;
        }
    }
}

// ==================================================================================
// Kernel 3: flash attention, 48KB STATIC smem, register softmax.
// Block = (64-query tile, bh). 256 threads, ty=t>>4 (m dir), tx=t&15 (n/d dir).
// Row m=ty*4+i is owned by the 16 tx-lanes of one half-warp -> shfl reductions,
// m/l/corr in registers (no softmax smem state).
// ==================================================================================
__global__ void __launch_bounds__(256) attn_kernel()
{
    __shared__ __align__(16) float Qt[64 * 64];   // [d][m]
    __shared__ __align__(16) float KS[64 * 64];   // Kt [d][n] -> P [m][n]
    __shared__ __align__(16) float Vs[64 * 64];   // [j][d]

    int bh = blockIdx.y;            // b*16 + h
    int q0 = blockIdx.x * 64;
    const float* qp = g_q + (size_t)bh * (S_ * HD);   // [d][s], stride S_
    const float* kp = g_k + (size_t)bh * (S_ * HD);   // [d][s], stride S_
    const float* vp = g_v + (size_t)bh * (S_ * HD);   // [s][d]

    int t  = threadIdx.x;
    int tx = t & 15;                // n / d quadrant
    int ty = t >> 4;                // m quadrant

    // ---- load Q tile: Qt[d][m] directly from transposed layout (coalesced) ----
#pragma unroll
    for (int p = 0; p < 4; p++) {
        int idx = t + p * 256;      // 1024 float4s
        int d   = idx >> 4;         // 0..63
        int m4  = idx & 15;
        float4 q = *(const float4*)(qp + (size_t)d * S_ + q0 + m4 * 4);
        *(float4*)&Qt[d * 64 + m4 * 4] = q;
    }

    const float SCALE = 0.03125f;   // 1/sqrt(1024)
    float O[4][4], mrow[4], lrow[4];
#pragma unroll
    for (int i = 0; i < 4; i++) {
        mrow[i] = -INFINITY;
        lrow[i] = 0.0f;
#pragma unroll
        for (int j = 0; j < 4; j++) O[i][j] = 0.0f;
    }

    for (int tile = 0; tile < 32; ++tile) {
        int k0 = tile * 64;
        __syncthreads();            // prev tile consumed (tile 0: Qt also covered)

        // ---- load Kt[d][n] (from transposed K) and Vs[j][d] (natural) ----
#pragma unroll
        for (int p = 0; p < 4; p++) {
            int idx = t + p * 256;
            int r   = idx >> 4;
            int c4  = idx & 15;
            float4 kv = *(const float4*)(kp + (size_t)r * S_ + k0 + c4 * 4);
            *(float4*)&KS[r * 64 + c4 * 4] = kv;
            float4 vv = *(const float4*)(vp + (size_t)(k0 + r) * HD + c4 * 4);
            *(float4*)&Vs[r * 64 + c4 * 4] = vv;
        }
        __syncthreads();

        // ---- S = Q K^T : 4x4 microtile GEMM over d=64 ----
        float s[4][4];
#pragma unroll
        for (int i = 0; i < 4; i++)
#pragma unroll
            for (int j = 0; j < 4; j++) s[i][j] = 0.0f;

#pragma unroll 8
        for (int k = 0; k < 64; k++) {
            float4 a = *(const float4*)&Qt[k * 64 + ty * 4];
            float4 b = *(const float4*)&KS[k * 64 + tx * 4];
            float av[4] = {a.x, a.y, a.z, a.w};
            float bv[4] = {b.x, b.y, b.z, b.w};
#pragma unroll
            for (int i = 0; i < 4; i++)
#pragma unroll
                for (int j = 0; j < 4; j++)
                    s[i][j] += av[i] * bv[j];
        }

        // ---- register softmax: row reductions across the 16 tx-lanes ----
        float corr[4];
#pragma unroll
        for (int i = 0; i < 4; i++) {
#pragma unroll
            for (int j = 0; j < 4; j++) s[i][j] *= SCALE;
            float mx = fmaxf(fmaxf(s[i][0], s[i][1]), fmaxf(s[i][2], s[i][3]));
#pragma unroll
            for (int off = 1; off < 16; off <<= 1)
                mx = fmaxf(mx, __shfl_xor_sync(0xffffffffu, mx, off));
            float mnew = fmaxf(mrow[i], mx);
            corr[i] = __expf(mrow[i] - mnew);    // 0 on first tile
            float ts = 0.0f;
#pragma unroll
            for (int j = 0; j < 4; j++) {
                float e = __expf(s[i][j] - mnew);
                s[i][j] = e;
                ts += e;
            }
#pragma unroll
            for (int off = 1; off < 16; off <<= 1)
                ts += __shfl_xor_sync(0xffffffffu, ts, off);
            lrow[i] = lrow[i] * corr[i] + ts;
            mrow[i] = mnew;
        }

        __syncthreads();            // all Kt readers done -> safe to overwrite with P
#pragma unroll
        for (int i = 0; i < 4; i++)
            *(float4*)&KS[(ty * 4 + i) * 64 + tx * 4] =
                make_float4(s[i][0], s[i][1], s[i][2], s[i][3]);
        __syncthreads();            // P visible to all

        // ---- O = O*corr + P @ V : 4x4 microtile over j=64 ----
#pragma unroll
        for (int i = 0; i < 4; i++)
#pragma unroll
            for (int j = 0; j < 4; j++) O[i][j] *= corr[i];

#pragma unroll 4
        for (int j = 0; j < 64; j += 4) {
            float4 a0 = *(const float4*)&KS[(ty * 4 + 0) * 64 + j];
            float4 a1 = *(const float4*)&KS[(ty * 4 + 1) * 64 + j];
            float4 a2 = *(const float4*)&KS[(ty * 4 + 2) * 64 + j];
            float4 a3 = *(const float4*)&KS[(ty * 4 + 3) * 64 + j];
            float pa[4][4] = {{a0.x, a0.y, a0.z, a0.w},
                              {a1.x, a1.y, a1.z, a1.w},
                              {a2.x, a2.y, a2.z, a2.w},
                              {a3.x, a3.y, a3.z, a3.w}};
#pragma unroll
            for (int jj = 0; jj < 4; jj++) {
                float4 b = *(const float4*)&Vs[(j + jj) * 64 + tx * 4];
                float bv[4] = {b.x, b.y, b.z, b.w};
#pragma unroll
                for (int i = 0; i < 4; i++)
#pragma unroll
                    for (int d = 0; d < 4; d++)
                        O[i][d] += pa[i][jj] * bv[d];
            }
        }
    }

    // ---- epilogue: O / l, write [B,S,D] for O-projection ----
    int b_ = bh >> 4;
    int h  = bh & 15;
#pragma unroll
    for (int i = 0; i < 4; i++) {
        int m = q0 + ty * 4 + i;
        float inv = 1.0f / lrow[i];
        float4 v = make_float4(O[i][0] * inv, O[i][1] * inv,
                               O[i][2] * inv, O[i][3] * inv);
        *(float4*)(g_att + (size_t)(b_ * S_ + m) * D_ + h * HD + tx * 4) = v;
    }
}

// ==================================================================================
extern "C" void kernel_launch(void* const* d_in, const int* in_sizes, int n_in,
                              void* d_out, int out_size)
{
    const float* x     = (const float*)d_in[0];
    const float* rel   = (const float*)d_in[1];
    const float* alpha = (const float*)d_in[2];
    const float* Wq    = (const float*)d_in[3];
    const float* bq    = (const float*)d_in[4];
    const float* Wk    = (const float*)d_in[5];
    const float* bk    = (const float*)d_in[6];
    const float* Wv    = (const float*)d_in[7];
    const float* bv    = (const float*)d_in[8];
    const float* Wo    = (const float*)d_in[9];
    const float* bo    = (const float*)d_in[10];
    float* out = (float*)d_out;

    add_pe_kernel<<<M_, 256>>>(x, rel, alpha);
    gemm_kernel<<<dim3(8, 32, 3), 256>>>(1, Wq, Wk, Wv, bq, bk, bv, nullptr);
    attn_kernel<<<dim3(32, 32), 256>>>();
    gemm_kernel<<<dim3(8, 32, 1), 256>>>(0, Wo, Wo, Wo, bo, bo, bo, out);
}